// round 10
// baseline (speedup 1.0000x reference)
#include <cuda_runtime.h>
#include <math.h>

// LTC RNN, B=256 T=8192 I=6 U=64 M=16, 6 ODE unfolds.
// Round-10: TWO BATCHES PER CTA (grid 128, 1 CTA/SM, 128 thr). Every thread
// interleaves batch b0=2*bid and b1=2*bid+1 in registers: weights shared,
// only v/x/accums duplicate -> per-warp ILP doubles (64 independent synapse
// chains), one batch's reduce/div tail hides under the other's MUFU burst,
// and the attracting in-phase lock between co-resident CTAs (rounds 1-9)
// is eliminated because there is no partner CTA.
// Keeps round-9's PWL tanh LUT offload (1 of 4 sigmoids on fma/LSU pipes,
// 1024 segs over [-16,16), cvt-free magic-number indexing) and LDS.128
// v loads from padded ping-pong smem. 1 barrier per unfold (both batches).

#define T_LEN 8192
#define NI 6
#define NU 64
#define NM 16

static __device__ __forceinline__ float fast_tanh(float x) {
    float r; asm("tanh.approx.f32 %0, %1;" : "=f"(r) : "f"(x)); return r;
}
static __device__ __forceinline__ float fabs_bits(float v) {
    return __int_as_float(__float_as_int(v) & 0x7fffffff);
}
static __device__ __forceinline__ float lut_tanh(const float2* lutm512, float x) {
    float y = x + 96.0f;                       // [64,128) binade
    unsigned uu = __float_as_uint(y);
    unsigned idx = (uu >> 12) & 0x7FFu;        // segment + 512
    float2 sb = lutm512[idx];
    return fmaf(x, sb.x, sb.y);
}

__global__ __launch_bounds__(128, 1)
void ltc_kernel(const float* __restrict__ x,
                const float* __restrict__ gleak,
                const float* __restrict__ vleak,
                const float* __restrict__ cm,
                const float* __restrict__ sigma,
                const float* __restrict__ mu,
                const float* __restrict__ w,
                const float* __restrict__ erev,
                const float* __restrict__ s_sigma,
                const float* __restrict__ s_mu,
                const float* __restrict__ s_w,
                const float* __restrict__ s_erev,
                const float* __restrict__ in_w,
                const float* __restrict__ in_b,
                const float* __restrict__ out_w,
                const float* __restrict__ out_b,
                float* __restrict__ out)
{
    __shared__ __align__(16) float  vsm[2][2][72];  // [batch][pp][v at j+4*(j>>5)]
    __shared__ __align__(8)  float2 lut[1024];

    const int tid  = threadIdx.x;
    const int lane = tid & 31;
    const int wrp  = tid >> 5;
    const int q    = lane >> 4;
    const int u    = (wrp << 4) | (lane & 15);
    const int rbase = 36 * q;

    const long long b0 = 2LL * blockIdx.x;
    const long long b1 = b0 + 1;

    // build PWL tanh table
    for (int k = tid; k < 1024; k += 128) {
        float x0 = -16.0f + (float)k * (1.0f / 32.0f);
        float t0 = tanhf(x0);
        float t1 = tanhf(x0 + (1.0f / 32.0f));
        float s  = (t1 - t0) * 32.0f;
        lut[k] = make_float2(s, fmaf(-s, x0, t0));
    }
    const float2* lutm512 = lut - 512;

    const float gl   = gleak[u];
    const float cmt  = cm[u] * 6.0f;
    const float glvl = gl * vleak[u];
    const float denc = cmt + gl + 1e-8f;

    // 32 per-(j,u) constants — SHARED by both batches
    float cs[32], cc[32], we[32];
    float Cd = 0.f, Cn = 0.f;
#pragma unroll
    for (int jj = 0; jj < 32; jj++) {
        int j   = 32 * q + jj;
        int idx = j * NU + u;
        float s = 0.5f * sigma[idx];
        cs[jj]  = s;
        cc[jj]  = -mu[idx] * s;
        float wv = 0.5f * w[idx] * erev[idx];
        we[jj]  = wv;
        Cd += fabsf(wv);
        Cn += wv;
    }

    // sensory constants (shared weights; per-batch activations)
    float ss[3], sc2[3], swe[3], iw[3], ib[3];
    float sCd = 0.f, sCn = 0.f;
#pragma unroll
    for (int i = 0; i < 3; i++) {
        int ii  = 3 * q + i;
        int idx = ii * NU + u;
        float s = 0.5f * s_sigma[idx];
        ss[i]   = s;
        sc2[i]  = -s_mu[idx] * s;
        float wv = 0.5f * s_w[idx] * s_erev[idx];
        swe[i]  = wv;
        sCd += fabs_bits(wv);
        sCn += wv;
        iw[i] = in_w[ii];
        ib[i] = in_b[ii];
    }

    float ow = 0.f, ob = 0.f;
    if (tid < NM) { ow = out_w[tid]; ob = out_b[tid]; }

    if (q == 0) {
        vsm[0][0][u + 4 * (u >> 5)] = 0.f;
        vsm[1][0][u + 4 * (u >> 5)] = 0.f;
    }
    float vua = 0.f, vub = 0.f;

    const float* xba = x + b0 * T_LEN * NI + 3 * q;
    const float* xbb = x + b1 * T_LEN * NI + 3 * q;
    float xa0 = xba[0], xa1 = xba[1], xa2 = xba[2];
    float xb0 = xbb[0], xb1 = xbb[1], xb2 = xbb[2];
    float* outa = out + b0 * T_LEN * NM;
    float* outb = out + b1 * T_LEN * NM;

    __syncthreads();

    for (int t = 0; t < T_LEN; t++) {
        float a0 = xa0, a1 = xa1, a2 = xa2;
        float c0 = xb0, c1 = xb1, c2 = xb2;
        if (t + 1 < T_LEN) {
            const float* pa = xba + (size_t)(t + 1) * NI;
            const float* pb = xbb + (size_t)(t + 1) * NI;
            xa0 = pa[0]; xa1 = pa[1]; xa2 = pa[2];
            xb0 = pb[0]; xb1 = pb[1]; xb2 = pb[2];
        }

        // sensory synapses, both batches (MUFU; 6/step, negligible)
        float dsaA = sCd, nsaA = sCn, dsaB = sCd, nsaB = sCn;
#pragma unroll
        for (int i = 0; i < 3; i++) {
            float xiA = fmaf((i == 0 ? a0 : i == 1 ? a1 : a2), iw[i], ib[i]);
            float xiB = fmaf((i == 0 ? c0 : i == 1 ? c1 : c2), iw[i], ib[i]);
            float hA = fast_tanh(fmaf(xiA, ss[i], sc2[i]));
            float hB = fast_tanh(fmaf(xiB, ss[i], sc2[i]));
            dsaA = fmaf(fabs_bits(swe[i]), hA, dsaA);
            nsaA = fmaf(swe[i], hA, nsaA);
            dsaB = fmaf(fabs_bits(swe[i]), hB, dsaB);
            nsaB = fmaf(swe[i], hB, nsaB);
        }
        dsaA += __shfl_xor_sync(0xffffffffu, dsaA, 16);
        nsaA += __shfl_xor_sync(0xffffffffu, nsaA, 16);
        dsaB += __shfl_xor_sync(0xffffffffu, dsaB, 16);
        nsaB += __shfl_xor_sync(0xffffffffu, nsaB, 16);
        float denA = denc + dsaA, numA = glvl + nsaA;
        float denB = denc + dsaB, numB = glvl + nsaB;

        // 6 unfolds, both batches fused (per group: 3 MUFU + 1 LUT, x2)
#pragma unroll
        for (int k = 0; k < 6; k++) {
            const float4* vrA =
                reinterpret_cast<const float4*>(&vsm[0][k & 1][rbase]);
            const float4* vrB =
                reinterpret_cast<const float4*>(&vsm[1][k & 1][rbase]);
            float anA0 = Cn, anA1 = 0.f, adA0 = Cd, adA1 = 0.f;
            float anB0 = Cn, anB1 = 0.f, adB0 = Cd, adB1 = 0.f;
#pragma unroll
            for (int p = 0; p < 8; p++) {
                float4 vA = vrA[p];
                float4 vB = vrB[p];
                float hA0 = fast_tanh(fmaf(vA.x, cs[4*p],   cc[4*p]));
                float hB0 = fast_tanh(fmaf(vB.x, cs[4*p],   cc[4*p]));
                float hA1 = fast_tanh(fmaf(vA.y, cs[4*p+1], cc[4*p+1]));
                float hB1 = fast_tanh(fmaf(vB.y, cs[4*p+1], cc[4*p+1]));
                float hA2 = fast_tanh(fmaf(vA.z, cs[4*p+2], cc[4*p+2]));
                float hB2 = fast_tanh(fmaf(vB.z, cs[4*p+2], cc[4*p+2]));
                float hA3 = lut_tanh(lutm512, fmaf(vA.w, cs[4*p+3], cc[4*p+3]));
                float hB3 = lut_tanh(lutm512, fmaf(vB.w, cs[4*p+3], cc[4*p+3]));
                float w0 = we[4*p],   w1 = we[4*p+1];
                float w2 = we[4*p+2], w3 = we[4*p+3];
                anA0 = fmaf(w0, hA0, anA0);  adA0 = fmaf(fabs_bits(w0), hA0, adA0);
                anB0 = fmaf(w0, hB0, anB0);  adB0 = fmaf(fabs_bits(w0), hB0, adB0);
                anA1 = fmaf(w1, hA1, anA1);  adA1 = fmaf(fabs_bits(w1), hA1, adA1);
                anB1 = fmaf(w1, hB1, anB1);  adB1 = fmaf(fabs_bits(w1), hB1, adB1);
                anA0 = fmaf(w2, hA2, anA0);  adA0 = fmaf(fabs_bits(w2), hA2, adA0);
                anB0 = fmaf(w2, hB2, anB0);  adB0 = fmaf(fabs_bits(w2), hB2, adB0);
                anA1 = fmaf(w3, hA3, anA1);  adA1 = fmaf(fabs_bits(w3), hA3, adA1);
                anB1 = fmaf(w3, hB3, anB1);  adB1 = fmaf(fabs_bits(w3), hB3, adB1);
            }
            float anA = anA0 + anA1, adA = adA0 + adA1;
            float anB = anB0 + anB1, adB = adB0 + adB1;
            anA += __shfl_xor_sync(0xffffffffu, anA, 16);
            adA += __shfl_xor_sync(0xffffffffu, adA, 16);
            anB += __shfl_xor_sync(0xffffffffu, anB, 16);
            adB += __shfl_xor_sync(0xffffffffu, adB, 16);
            float nA = fmaf(cmt, vua, numA + anA);
            float nB = fmaf(cmt, vub, numB + anB);
            vua = __fdividef(nA, denA + adA);
            vub = __fdividef(nB, denB + adB);
            int nb = (k & 1) ^ 1;
            if (q == 0) {
                vsm[0][nb][u + 4 * (u >> 5)] = vua;
                vsm[1][nb][u + 4 * (u >> 5)] = vub;
            }
            __syncthreads();
        }

        if (tid < NM) {
            outa[(size_t)t * NM + tid] = fmaf(vua, ow, ob);
            outb[(size_t)t * NM + tid] = fmaf(vub, ow, ob);
        }
    }
}

extern "C" void kernel_launch(void* const* d_in, const int* in_sizes, int n_in,
                              void* d_out, int out_size) {
    (void)in_sizes; (void)n_in; (void)out_size;
    ltc_kernel<<<128, 128>>>(
        (const float*)d_in[0],  (const float*)d_in[1],  (const float*)d_in[2],
        (const float*)d_in[3],  (const float*)d_in[4],  (const float*)d_in[5],
        (const float*)d_in[6],  (const float*)d_in[7],  (const float*)d_in[8],
        (const float*)d_in[9],  (const float*)d_in[10], (const float*)d_in[11],
        (const float*)d_in[12], (const float*)d_in[13], (const float*)d_in[14],
        (const float*)d_in[15], (float*)d_out);
}

// round 11
// speedup vs baseline: 1.0610x; 1.0610x over previous
#include <cuda_runtime.h>
#include <math.h>

// LTC RNN, B=256 T=8192 I=6 U=64 M=16, 6 ODE unfolds.
// Round-11 = round-9 (best: 16.29ms) with the PWL-LUT tanh offload raised
// from 8/32 to 16/32 synapses per lane. Round-8->9 measured that cutting
// MUFU 512->384 cyc/SMSP-unfold bought only ~30cy -> MUFU no longer binds;
// with 16/32 offloaded, MUFU drops to 256 and issue (~340) balances it.
// Grid/block restored to 256x128 (round-10 proved 2 warps/SMSP of latency
// hiding beats doubled in-thread ILP at 1 warp/SMSP).
// LUT: 1024 PWL segments over [-16,16), step 1/32, max err 9.4e-5; cvt-free
// magic-number indexing ((bits(x+96)>>12)&0x7FF); args provably in-range
// (|v|<=~1.3 -> |arg|<=8.4). Sensory tanh (unbounded) stays on MUFU.

#define T_LEN 8192
#define NI 6
#define NU 64
#define NM 16

static __device__ __forceinline__ float fast_tanh(float x) {
    float r; asm("tanh.approx.f32 %0, %1;" : "=f"(r) : "f"(x)); return r;
}
static __device__ __forceinline__ float fabs_bits(float v) {
    return __int_as_float(__float_as_int(v) & 0x7fffffff);
}
static __device__ __forceinline__ float lut_tanh(const float2* lutm512, float x) {
    float y = x + 96.0f;                       // lands in binade [64,128)
    unsigned uu = __float_as_uint(y);
    unsigned idx = (uu >> 12) & 0x7FFu;        // segment + 512
    float2 sb = lutm512[idx];                  // (slope, intercept)
    return fmaf(x, sb.x, sb.y);
}

__global__ __launch_bounds__(128, 2)
void ltc_kernel(const float* __restrict__ x,
                const float* __restrict__ gleak,
                const float* __restrict__ vleak,
                const float* __restrict__ cm,
                const float* __restrict__ sigma,
                const float* __restrict__ mu,
                const float* __restrict__ w,
                const float* __restrict__ erev,
                const float* __restrict__ s_sigma,
                const float* __restrict__ s_mu,
                const float* __restrict__ s_w,
                const float* __restrict__ s_erev,
                const float* __restrict__ in_w,
                const float* __restrict__ in_b,
                const float* __restrict__ out_w,
                const float* __restrict__ out_b,
                float* __restrict__ out)
{
    __shared__ __align__(16) float  vsm[2][72];  // v[j] at j + 4*(j>>5)
    __shared__ __align__(8)  float2 lut[1024];   // PWL tanh segments

    const int b    = blockIdx.x;
    const int tid  = threadIdx.x;
    const int lane = tid & 31;
    const int wrp  = tid >> 5;
    const int q    = lane >> 4;
    const int u    = (wrp << 4) | (lane & 15);
    const int rbase = 36 * q;

    // build PWL tanh table (setup only)
    for (int k = tid; k < 1024; k += 128) {
        float x0 = -16.0f + (float)k * (1.0f / 32.0f);
        float t0 = tanhf(x0);
        float t1 = tanhf(x0 + (1.0f / 32.0f));
        float s  = (t1 - t0) * 32.0f;
        lut[k] = make_float2(s, fmaf(-s, x0, t0));
    }
    const float2* lutm512 = lut - 512;

    const float gl   = gleak[u];
    const float cmt  = cm[u] * 6.0f;
    const float glvl = gl * vleak[u];
    const float denc = cmt + gl + 1e-8f;

    // 32 per-(j,u) constants in registers
    float cs[32], cc[32], we[32];
    float Cd = 0.f, Cn = 0.f;
#pragma unroll
    for (int jj = 0; jj < 32; jj++) {
        int j   = 32 * q + jj;
        int idx = j * NU + u;
        float s = 0.5f * sigma[idx];
        cs[jj]  = s;
        cc[jj]  = -mu[idx] * s;
        float wv = 0.5f * w[idx] * erev[idx];
        we[jj]  = wv;
        Cd += fabsf(wv);
        Cn += wv;
    }

    // sensory constants: lane half q handles inputs [3q, 3q+3)
    float ss[3], sc2[3], swe[3], iw[3], ib[3];
    float sCd = 0.f, sCn = 0.f;
#pragma unroll
    for (int i = 0; i < 3; i++) {
        int ii  = 3 * q + i;
        int idx = ii * NU + u;
        float s = 0.5f * s_sigma[idx];
        ss[i]   = s;
        sc2[i]  = -s_mu[idx] * s;
        float wv = 0.5f * s_w[idx] * s_erev[idx];
        swe[i]  = wv;
        sCd += fabsf(wv);
        sCn += wv;
        iw[i] = in_w[ii];
        ib[i] = in_b[ii];
    }

    float ow = 0.f, ob = 0.f;
    if (tid < NM) { ow = out_w[tid]; ob = out_b[tid]; }

    if (q == 0) vsm[0][u + 4 * (u >> 5)] = 0.f;
    float vu = 0.f;

    const float* xb = x + (long long)b * T_LEN * NI + 3 * q;
    float xr0 = xb[0], xr1 = xb[1], xr2 = xb[2];
    float* outp = out + (long long)b * T_LEN * NM;

    __syncthreads();

    for (int t = 0; t < T_LEN; t++) {
        float x0 = xr0, x1 = xr1, x2 = xr2;
        if (t + 1 < T_LEN) {
            const float* xn = xb + (size_t)(t + 1) * NI;
            xr0 = xn[0]; xr1 = xn[1]; xr2 = xn[2];
        }

        // sensory synapses (unbounded args -> MUFU; constant across unfolds)
        float xi0 = fmaf(x0, iw[0], ib[0]);
        float xi1 = fmaf(x1, iw[1], ib[1]);
        float xi2 = fmaf(x2, iw[2], ib[2]);
        float dsa = sCd, nsa = sCn, h;
        h = fast_tanh(fmaf(xi0, ss[0], sc2[0]));
        dsa = fmaf(fabs_bits(swe[0]), h, dsa);  nsa = fmaf(swe[0], h, nsa);
        h = fast_tanh(fmaf(xi1, ss[1], sc2[1]));
        dsa = fmaf(fabs_bits(swe[1]), h, dsa);  nsa = fmaf(swe[1], h, nsa);
        h = fast_tanh(fmaf(xi2, ss[2], sc2[2]));
        dsa = fmaf(fabs_bits(swe[2]), h, dsa);  nsa = fmaf(swe[2], h, nsa);
        dsa += __shfl_xor_sync(0xffffffffu, dsa, 16);
        nsa += __shfl_xor_sync(0xffffffffu, nsa, 16);
        float den_b = denc + dsa;
        float num_b = glvl + nsa;

        // 6 semi-implicit Euler unfolds; per float4 group: 2 MUFU + 2 LUT
#pragma unroll
        for (int k = 0; k < 6; k++) {
            const float4* vr4 =
                reinterpret_cast<const float4*>(&vsm[k & 1][rbase]);
            float an0 = Cn, an1 = 0.f, ad0 = Cd, ad1 = 0.f;
#pragma unroll
            for (int p = 0; p < 8; p++) {
                float4 v4 = vr4[p];                         // LDS.128
                float h0 = fast_tanh(fmaf(v4.x, cs[4*p],   cc[4*p]));
                float h1 = fast_tanh(fmaf(v4.y, cs[4*p+1], cc[4*p+1]));
                float h2 = lut_tanh(lutm512,
                                    fmaf(v4.z, cs[4*p+2], cc[4*p+2]));
                float h3 = lut_tanh(lutm512,
                                    fmaf(v4.w, cs[4*p+3], cc[4*p+3]));
                float w0 = we[4*p],   w1 = we[4*p+1];
                float w2 = we[4*p+2], w3 = we[4*p+3];
                an0 = fmaf(w0, h0, an0);  ad0 = fmaf(fabs_bits(w0), h0, ad0);
                an1 = fmaf(w1, h1, an1);  ad1 = fmaf(fabs_bits(w1), h1, ad1);
                an0 = fmaf(w2, h2, an0);  ad0 = fmaf(fabs_bits(w2), h2, ad0);
                an1 = fmaf(w3, h3, an1);  ad1 = fmaf(fabs_bits(w3), h3, ad1);
            }
            float an = an0 + an1, ad = ad0 + ad1;
            an += __shfl_xor_sync(0xffffffffu, an, 16);
            ad += __shfl_xor_sync(0xffffffffu, ad, 16);
            float num = fmaf(cmt, vu, num_b + an);
            vu = __fdividef(num, den_b + ad);
            if (q == 0) vsm[(k & 1) ^ 1][u + 4 * (u >> 5)] = vu;
            __syncthreads();
        }

        if (tid < NM) outp[(size_t)t * NM + tid] = fmaf(vu, ow, ob);
    }
}

extern "C" void kernel_launch(void* const* d_in, const int* in_sizes, int n_in,
                              void* d_out, int out_size) {
    (void)in_sizes; (void)n_in; (void)out_size;
    ltc_kernel<<<256, 128>>>(
        (const float*)d_in[0],  (const float*)d_in[1],  (const float*)d_in[2],
        (const float*)d_in[3],  (const float*)d_in[4],  (const float*)d_in[5],
        (const float*)d_in[6],  (const float*)d_in[7],  (const float*)d_in[8],
        (const float*)d_in[9],  (const float*)d_in[10], (const float*)d_in[11],
        (const float*)d_in[12], (const float*)d_in[13], (const float*)d_in[14],
        (const float*)d_in[15], (float*)d_out);
}

// round 12
// speedup vs baseline: 1.5037x; 1.4173x over previous
#include <cuda_runtime.h>
#include <math.h>

// LTC RNN, B=256 T=8192 I=6 U=64 M=16, 6 ODE unfolds.
// Round-12 = round-9 math (3:1 MUFU:PWL-LUT sigmoid mix — measured optimum;
// 16/32 LUT saturated the L1 crossbar in round-11) repackaged as:
//   grid 128, block 256: each CTA carries TWO independent 128-thread batch
//   groups with SEPARATE NAMED BARRIERS (bar.sync 1/2, 128). Every SM gets
//   exactly one CTA = 2 batches (same per-SM work as the old 2-CTA case),
//   but the groups never synchronize -> one group's per-unfold serial tail
//   (shfl+div+store+barrier) overlaps the other group's MUFU burst, which
//   the attracting in-phase lock prevented in the 2-CTA layout (r8).
// Per group: round-1 layout (warp w: units [16w,16w+16); lane half q covers
// j in [32q,32q+32)); constants in regs; LDS.128 v loads from padded
// ping-pong smem; per float4 group 3 MUFU tanh + 1 PWL-LUT tanh (1024 segs
// over [-16,16), cvt-free magic indexing; args provably in [-8.5,8.5]).

#define T_LEN 8192
#define NI 6
#define NU 64
#define NM 16

static __device__ __forceinline__ float fast_tanh(float x) {
    float r; asm("tanh.approx.f32 %0, %1;" : "=f"(r) : "f"(x)); return r;
}
static __device__ __forceinline__ float fabs_bits(float v) {
    return __int_as_float(__float_as_int(v) & 0x7fffffff);
}
static __device__ __forceinline__ float lut_tanh(const float2* lutm512, float x) {
    float y = x + 96.0f;                       // lands in binade [64,128)
    unsigned uu = __float_as_uint(y);
    unsigned idx = (uu >> 12) & 0x7FFu;        // segment + 512
    float2 sb = lutm512[idx];                  // (slope, intercept)
    return fmaf(x, sb.x, sb.y);
}
static __device__ __forceinline__ void group_bar(int name) {
    asm volatile("bar.sync %0, 128;" :: "r"(name) : "memory");
}

__global__ __launch_bounds__(256, 1)
void ltc_kernel(const float* __restrict__ x,
                const float* __restrict__ gleak,
                const float* __restrict__ vleak,
                const float* __restrict__ cm,
                const float* __restrict__ sigma,
                const float* __restrict__ mu,
                const float* __restrict__ w,
                const float* __restrict__ erev,
                const float* __restrict__ s_sigma,
                const float* __restrict__ s_mu,
                const float* __restrict__ s_w,
                const float* __restrict__ s_erev,
                const float* __restrict__ in_w,
                const float* __restrict__ in_b,
                const float* __restrict__ out_w,
                const float* __restrict__ out_b,
                float* __restrict__ out)
{
    __shared__ __align__(16) float  vsm[2][2][72]; // [group][pp][v at j+4*(j>>5)]
    __shared__ __align__(8)  float2 lut[1024];     // PWL tanh (read-only in loop)

    const int tid  = threadIdx.x;
    const int wg   = tid >> 7;                 // batch group 0/1
    const int gtid = tid & 127;                // tid within group
    const int lane = tid & 31;
    const int wrp  = gtid >> 5;                // warp within group 0..3
    const int q    = lane >> 4;
    const int u    = (wrp << 4) | (lane & 15);
    const int rbase = 36 * q;
    const int barid = wg + 1;                  // named barrier per group

    const long long b = 2LL * blockIdx.x + wg;

    // build PWL tanh table (all 256 threads), one full sync, then groups
    // free-run on their own named barriers.
    for (int k = tid; k < 1024; k += 256) {
        float x0 = -16.0f + (float)k * (1.0f / 32.0f);
        float t0 = tanhf(x0);
        float t1 = tanhf(x0 + (1.0f / 32.0f));
        float s  = (t1 - t0) * 32.0f;
        lut[k] = make_float2(s, fmaf(-s, x0, t0));
    }
    const float2* lutm512 = lut - 512;

    const float gl   = gleak[u];
    const float cmt  = cm[u] * 6.0f;
    const float glvl = gl * vleak[u];
    const float denc = cmt + gl + 1e-8f;

    // 32 per-(j,u) constants in registers
    float cs[32], cc[32], we[32];
    float Cd = 0.f, Cn = 0.f;
#pragma unroll
    for (int jj = 0; jj < 32; jj++) {
        int j   = 32 * q + jj;
        int idx = j * NU + u;
        float s = 0.5f * sigma[idx];
        cs[jj]  = s;
        cc[jj]  = -mu[idx] * s;
        float wv = 0.5f * w[idx] * erev[idx];
        we[jj]  = wv;
        Cd += fabsf(wv);
        Cn += wv;
    }

    // sensory constants: lane half q handles inputs [3q, 3q+3)
    float ss[3], sc2[3], swe[3], iw[3], ib[3];
    float sCd = 0.f, sCn = 0.f;
#pragma unroll
    for (int i = 0; i < 3; i++) {
        int ii  = 3 * q + i;
        int idx = ii * NU + u;
        float s = 0.5f * s_sigma[idx];
        ss[i]   = s;
        sc2[i]  = -s_mu[idx] * s;
        float wv = 0.5f * s_w[idx] * s_erev[idx];
        swe[i]  = wv;
        sCd += fabsf(wv);
        sCn += wv;
        iw[i] = in_w[ii];
        ib[i] = in_b[ii];
    }

    float ow = 0.f, ob = 0.f;
    if (gtid < NM) { ow = out_w[gtid]; ob = out_b[gtid]; }

    if (q == 0) vsm[wg][0][u + 4 * (u >> 5)] = 0.f;
    float vu = 0.f;

    const float* xb = x + b * T_LEN * NI + 3 * q;
    float xr0 = xb[0], xr1 = xb[1], xr2 = xb[2];
    float* outp = out + b * T_LEN * NM;

    __syncthreads();   // LUT + v init visible to all; groups decouple after

    for (int t = 0; t < T_LEN; t++) {
        float x0 = xr0, x1 = xr1, x2 = xr2;
        if (t + 1 < T_LEN) {
            const float* xn = xb + (size_t)(t + 1) * NI;
            xr0 = xn[0]; xr1 = xn[1]; xr2 = xn[2];
        }

        // sensory synapses (unbounded args -> MUFU; constant across unfolds)
        float xi0 = fmaf(x0, iw[0], ib[0]);
        float xi1 = fmaf(x1, iw[1], ib[1]);
        float xi2 = fmaf(x2, iw[2], ib[2]);
        float dsa = sCd, nsa = sCn, h;
        h = fast_tanh(fmaf(xi0, ss[0], sc2[0]));
        dsa = fmaf(fabs_bits(swe[0]), h, dsa);  nsa = fmaf(swe[0], h, nsa);
        h = fast_tanh(fmaf(xi1, ss[1], sc2[1]));
        dsa = fmaf(fabs_bits(swe[1]), h, dsa);  nsa = fmaf(swe[1], h, nsa);
        h = fast_tanh(fmaf(xi2, ss[2], sc2[2]));
        dsa = fmaf(fabs_bits(swe[2]), h, dsa);  nsa = fmaf(swe[2], h, nsa);
        dsa += __shfl_xor_sync(0xffffffffu, dsa, 16);
        nsa += __shfl_xor_sync(0xffffffffu, nsa, 16);
        float den_b = denc + dsa;
        float num_b = glvl + nsa;

        // 6 semi-implicit Euler unfolds; per float4 group: 3 MUFU + 1 LUT
#pragma unroll
        for (int k = 0; k < 6; k++) {
            const float4* vr4 =
                reinterpret_cast<const float4*>(&vsm[wg][k & 1][rbase]);
            float an0 = Cn, an1 = 0.f, ad0 = Cd, ad1 = 0.f;
#pragma unroll
            for (int p = 0; p < 8; p++) {
                float4 v4 = vr4[p];                         // LDS.128
                float h0 = fast_tanh(fmaf(v4.x, cs[4*p],   cc[4*p]));
                float h1 = fast_tanh(fmaf(v4.y, cs[4*p+1], cc[4*p+1]));
                float h2 = fast_tanh(fmaf(v4.z, cs[4*p+2], cc[4*p+2]));
                float h3 = lut_tanh(lutm512,
                                    fmaf(v4.w, cs[4*p+3], cc[4*p+3]));
                float w0 = we[4*p],   w1 = we[4*p+1];
                float w2 = we[4*p+2], w3 = we[4*p+3];
                an0 = fmaf(w0, h0, an0);  ad0 = fmaf(fabs_bits(w0), h0, ad0);
                an1 = fmaf(w1, h1, an1);  ad1 = fmaf(fabs_bits(w1), h1, ad1);
                an0 = fmaf(w2, h2, an0);  ad0 = fmaf(fabs_bits(w2), h2, ad0);
                an1 = fmaf(w3, h3, an1);  ad1 = fmaf(fabs_bits(w3), h3, ad1);
            }
            float an = an0 + an1, ad = ad0 + ad1;
            an += __shfl_xor_sync(0xffffffffu, an, 16);
            ad += __shfl_xor_sync(0xffffffffu, ad, 16);
            float num = fmaf(cmt, vu, num_b + an);
            vu = __fdividef(num, den_b + ad);
            if (q == 0) vsm[wg][(k & 1) ^ 1][u + 4 * (u >> 5)] = vu;
            group_bar(barid);                  // group-private barrier
        }

        if (gtid < NM) outp[(size_t)t * NM + gtid] = fmaf(vu, ow, ob);
    }
}

extern "C" void kernel_launch(void* const* d_in, const int* in_sizes, int n_in,
                              void* d_out, int out_size) {
    (void)in_sizes; (void)n_in; (void)out_size;
    ltc_kernel<<<128, 256>>>(
        (const float*)d_in[0],  (const float*)d_in[1],  (const float*)d_in[2],
        (const float*)d_in[3],  (const float*)d_in[4],  (const float*)d_in[5],
        (const float*)d_in[6],  (const float*)d_in[7],  (const float*)d_in[8],
        (const float*)d_in[9],  (const float*)d_in[10], (const float*)d_in[11],
        (const float*)d_in[12], (const float*)d_in[13], (const float*)d_in[14],
        (const float*)d_in[15], (float*)d_out);
}

// round 13
// speedup vs baseline: 1.7594x; 1.1700x over previous
#include <cuda_runtime.h>
#include <math.h>

// LTC RNN, B=256 T=8192 I=6 U=64 M=16, 6 ODE unfolds.
// Round-13 = round-9 inner loop (best: 16.29ms) + TEMPORAL CHUNKING.
// The LTC step map is strongly contracting (calibrated rho_step ~ 0.01-0.4
// worst-case), so a chunk may start from v=0 at t0-K and run K=24 warmup
// steps: initial-condition error <= 0.4^24 ~ 3e-10 by the seam. Each batch
// splits into C=8 chunks of 1024 steps -> 2048 equal jobs over 296 resident
// slots (6.9 waves, HW work-stealing balance) instead of 256 jobs that left
// 40 of 148 SMs half-idle. Per-slot work drops 8192 -> ~7280 steps (-11%).
// Inner loop unchanged: 128 thr, warp w owns units [16w,16w+16), lane half
// q covers j in [32q,32q+32); constants in regs; LDS.128 v loads from
// padded ping-pong smem; per float4 group 3 MUFU tanh + 1 PWL-LUT tanh
// (1024 segs over [-16,16), cvt-free magic indexing). 1 barrier/unfold.

#define T_LEN 8192
#define NI 6
#define NU 64
#define NM 16
#define CHUNKS 8
#define CHUNK_B (T_LEN / CHUNKS)   // 1024
#define WARMUP 24

static __device__ __forceinline__ float fast_tanh(float x) {
    float r; asm("tanh.approx.f32 %0, %1;" : "=f"(r) : "f"(x)); return r;
}
static __device__ __forceinline__ float fabs_bits(float v) {
    return __int_as_float(__float_as_int(v) & 0x7fffffff);
}
static __device__ __forceinline__ float lut_tanh(const float2* lutm512, float x) {
    float y = x + 96.0f;                       // lands in binade [64,128)
    unsigned uu = __float_as_uint(y);
    unsigned idx = (uu >> 12) & 0x7FFu;        // segment + 512
    float2 sb = lutm512[idx];                  // (slope, intercept)
    return fmaf(x, sb.x, sb.y);
}

__global__ __launch_bounds__(128, 2)
void ltc_kernel(const float* __restrict__ x,
                const float* __restrict__ gleak,
                const float* __restrict__ vleak,
                const float* __restrict__ cm,
                const float* __restrict__ sigma,
                const float* __restrict__ mu,
                const float* __restrict__ w,
                const float* __restrict__ erev,
                const float* __restrict__ s_sigma,
                const float* __restrict__ s_mu,
                const float* __restrict__ s_w,
                const float* __restrict__ s_erev,
                const float* __restrict__ in_w,
                const float* __restrict__ in_b,
                const float* __restrict__ out_w,
                const float* __restrict__ out_b,
                float* __restrict__ out)
{
    __shared__ __align__(16) float  vsm[2][72];  // v[j] at j + 4*(j>>5)
    __shared__ __align__(8)  float2 lut[1024];   // PWL tanh segments

    const int bid  = blockIdx.x;
    const int b    = bid >> 3;                 // batch
    const int ch   = bid & (CHUNKS - 1);       // chunk within batch
    const int tid  = threadIdx.x;
    const int lane = tid & 31;
    const int wrp  = tid >> 5;
    const int q    = lane >> 4;
    const int u    = (wrp << 4) | (lane & 15);
    const int rbase = 36 * q;

    // time window: warmup from v=0 (contraction kills the seam error)
    const int twrite = ch * CHUNK_B;
    const int tstart = (ch == 0) ? 0 : (twrite - WARMUP);
    const int tend   = twrite + CHUNK_B;

    // build PWL tanh table (setup only)
    for (int k = tid; k < 1024; k += 128) {
        float x0 = -16.0f + (float)k * (1.0f / 32.0f);
        float t0 = tanhf(x0);
        float t1 = tanhf(x0 + (1.0f / 32.0f));
        float s  = (t1 - t0) * 32.0f;
        lut[k] = make_float2(s, fmaf(-s, x0, t0));
    }
    const float2* lutm512 = lut - 512;

    const float gl   = gleak[u];
    const float cmt  = cm[u] * 6.0f;
    const float glvl = gl * vleak[u];
    const float denc = cmt + gl + 1e-8f;

    // 32 per-(j,u) constants in registers
    float cs[32], cc[32], we[32];
    float Cd = 0.f, Cn = 0.f;
#pragma unroll
    for (int jj = 0; jj < 32; jj++) {
        int j   = 32 * q + jj;
        int idx = j * NU + u;
        float s = 0.5f * sigma[idx];
        cs[jj]  = s;
        cc[jj]  = -mu[idx] * s;
        float wv = 0.5f * w[idx] * erev[idx];
        we[jj]  = wv;
        Cd += fabsf(wv);
        Cn += wv;
    }

    // sensory constants: lane half q handles inputs [3q, 3q+3)
    float ss[3], sc2[3], swe[3], iw[3], ib[3];
    float sCd = 0.f, sCn = 0.f;
#pragma unroll
    for (int i = 0; i < 3; i++) {
        int ii  = 3 * q + i;
        int idx = ii * NU + u;
        float s = 0.5f * s_sigma[idx];
        ss[i]   = s;
        sc2[i]  = -s_mu[idx] * s;
        float wv = 0.5f * s_w[idx] * s_erev[idx];
        swe[i]  = wv;
        sCd += fabsf(wv);
        sCn += wv;
        iw[i] = in_w[ii];
        ib[i] = in_b[ii];
    }

    float ow = 0.f, ob = 0.f;
    if (tid < NM) { ow = out_w[tid]; ob = out_b[tid]; }

    if (q == 0) vsm[0][u + 4 * (u >> 5)] = 0.f;
    float vu = 0.f;

    const float* xb = x + (long long)b * T_LEN * NI + 3 * q;
    float xr0 = xb[(size_t)tstart * NI + 0];
    float xr1 = xb[(size_t)tstart * NI + 1];
    float xr2 = xb[(size_t)tstart * NI + 2];
    float* outp = out + (long long)b * T_LEN * NM;

    __syncthreads();

    for (int t = tstart; t < tend; t++) {
        float x0 = xr0, x1 = xr1, x2 = xr2;
        if (t + 1 < tend) {
            const float* xn = xb + (size_t)(t + 1) * NI;
            xr0 = xn[0]; xr1 = xn[1]; xr2 = xn[2];
        }

        // sensory synapses (unbounded args -> MUFU; constant across unfolds)
        float xi0 = fmaf(x0, iw[0], ib[0]);
        float xi1 = fmaf(x1, iw[1], ib[1]);
        float xi2 = fmaf(x2, iw[2], ib[2]);
        float dsa = sCd, nsa = sCn, h;
        h = fast_tanh(fmaf(xi0, ss[0], sc2[0]));
        dsa = fmaf(fabs_bits(swe[0]), h, dsa);  nsa = fmaf(swe[0], h, nsa);
        h = fast_tanh(fmaf(xi1, ss[1], sc2[1]));
        dsa = fmaf(fabs_bits(swe[1]), h, dsa);  nsa = fmaf(swe[1], h, nsa);
        h = fast_tanh(fmaf(xi2, ss[2], sc2[2]));
        dsa = fmaf(fabs_bits(swe[2]), h, dsa);  nsa = fmaf(swe[2], h, nsa);
        dsa += __shfl_xor_sync(0xffffffffu, dsa, 16);
        nsa += __shfl_xor_sync(0xffffffffu, nsa, 16);
        float den_b = denc + dsa;
        float num_b = glvl + nsa;

        // 6 semi-implicit Euler unfolds; per float4 group: 3 MUFU + 1 LUT
#pragma unroll
        for (int k = 0; k < 6; k++) {
            const float4* vr4 =
                reinterpret_cast<const float4*>(&vsm[k & 1][rbase]);
            float an0 = Cn, an1 = 0.f, ad0 = Cd, ad1 = 0.f;
#pragma unroll
            for (int p = 0; p < 8; p++) {
                float4 v4 = vr4[p];                         // LDS.128
                float h0 = fast_tanh(fmaf(v4.x, cs[4*p],   cc[4*p]));
                float h1 = fast_tanh(fmaf(v4.y, cs[4*p+1], cc[4*p+1]));
                float h2 = fast_tanh(fmaf(v4.z, cs[4*p+2], cc[4*p+2]));
                float h3 = lut_tanh(lutm512,
                                    fmaf(v4.w, cs[4*p+3], cc[4*p+3]));
                float w0 = we[4*p],   w1 = we[4*p+1];
                float w2 = we[4*p+2], w3 = we[4*p+3];
                an0 = fmaf(w0, h0, an0);  ad0 = fmaf(fabs_bits(w0), h0, ad0);
                an1 = fmaf(w1, h1, an1);  ad1 = fmaf(fabs_bits(w1), h1, ad1);
                an0 = fmaf(w2, h2, an0);  ad0 = fmaf(fabs_bits(w2), h2, ad0);
                an1 = fmaf(w3, h3, an1);  ad1 = fmaf(fabs_bits(w3), h3, ad1);
            }
            float an = an0 + an1, ad = ad0 + ad1;
            an += __shfl_xor_sync(0xffffffffu, an, 16);
            ad += __shfl_xor_sync(0xffffffffu, ad, 16);
            float num = fmaf(cmt, vu, num_b + an);
            vu = __fdividef(num, den_b + ad);
            if (q == 0) vsm[(k & 1) ^ 1][u + 4 * (u >> 5)] = vu;
            __syncthreads();
        }

        if (tid < NM && t >= twrite)
            outp[(size_t)t * NM + tid] = fmaf(vu, ow, ob);
    }
}

extern "C" void kernel_launch(void* const* d_in, const int* in_sizes, int n_in,
                              void* d_out, int out_size) {
    (void)in_sizes; (void)n_in; (void)out_size;
    ltc_kernel<<<256 * CHUNKS, 128>>>(
        (const float*)d_in[0],  (const float*)d_in[1],  (const float*)d_in[2],
        (const float*)d_in[3],  (const float*)d_in[4],  (const float*)d_in[5],
        (const float*)d_in[6],  (const float*)d_in[7],  (const float*)d_in[8],
        (const float*)d_in[9],  (const float*)d_in[10], (const float*)d_in[11],
        (const float*)d_in[12], (const float*)d_in[13], (const float*)d_in[14],
        (const float*)d_in[15], (float*)d_out);
}

// round 14
// speedup vs baseline: 1.7905x; 1.0177x over previous
#include <cuda_runtime.h>
#include <math.h>

// LTC RNN, B=256 T=8192 I=6 U=64 M=16, 6 ODE unfolds.
// Round-14 = round-13 (temporal chunking, best: 14.71ms) +
//  (a) software-pipelined sensory block: den_b/num_b for step t+1 are
//      computed INSIDE unfold k==2 of step t (x(t+1) is already prefetched),
//      so the ~100cy sensory chain overlaps the unfold burst instead of
//      sitting serially between steps;
//  (b) WARMUP 24 -> 16 (seam error at K=24 measured below resolution;
//      worst-case rho^16 ~ 4e-7 << 7.3e-5 noise floor).
// Chunking: C=8 chunks of 1024 steps/batch -> 2048 equal jobs over 296
// resident slots (7 waves); chunks ch>0 warm up from v=0 for 16 steps.
// Inner loop: 128 thr, warp w owns units [16w,16w+16), lane half q covers
// j in [32q,32q+32); constants in regs; LDS.128 v loads from padded
// ping-pong smem; per float4 group 3 MUFU tanh + 1 PWL-LUT tanh (1024 segs
// over [-16,16), cvt-free magic indexing). 1 barrier per unfold.

#define T_LEN 8192
#define NI 6
#define NU 64
#define NM 16
#define CHUNKS 8
#define CHUNK_B (T_LEN / CHUNKS)   // 1024
#define WARMUP 16

static __device__ __forceinline__ float fast_tanh(float x) {
    float r; asm("tanh.approx.f32 %0, %1;" : "=f"(r) : "f"(x)); return r;
}
static __device__ __forceinline__ float fabs_bits(float v) {
    return __int_as_float(__float_as_int(v) & 0x7fffffff);
}
static __device__ __forceinline__ float lut_tanh(const float2* lutm512, float x) {
    float y = x + 96.0f;                       // lands in binade [64,128)
    unsigned uu = __float_as_uint(y);
    unsigned idx = (uu >> 12) & 0x7FFu;        // segment + 512
    float2 sb = lutm512[idx];                  // (slope, intercept)
    return fmaf(x, sb.x, sb.y);
}

__global__ __launch_bounds__(128, 2)
void ltc_kernel(const float* __restrict__ x,
                const float* __restrict__ gleak,
                const float* __restrict__ vleak,
                const float* __restrict__ cm,
                const float* __restrict__ sigma,
                const float* __restrict__ mu,
                const float* __restrict__ w,
                const float* __restrict__ erev,
                const float* __restrict__ s_sigma,
                const float* __restrict__ s_mu,
                const float* __restrict__ s_w,
                const float* __restrict__ s_erev,
                const float* __restrict__ in_w,
                const float* __restrict__ in_b,
                const float* __restrict__ out_w,
                const float* __restrict__ out_b,
                float* __restrict__ out)
{
    __shared__ __align__(16) float  vsm[2][72];  // v[j] at j + 4*(j>>5)
    __shared__ __align__(8)  float2 lut[1024];   // PWL tanh segments

    const int bid  = blockIdx.x;
    const int b    = bid >> 3;                 // batch
    const int ch   = bid & (CHUNKS - 1);       // chunk within batch
    const int tid  = threadIdx.x;
    const int lane = tid & 31;
    const int wrp  = tid >> 5;
    const int q    = lane >> 4;
    const int u    = (wrp << 4) | (lane & 15);
    const int rbase = 36 * q;

    // time window: warmup from v=0 (contraction kills the seam error)
    const int twrite = ch * CHUNK_B;
    const int tstart = (ch == 0) ? 0 : (twrite - WARMUP);
    const int tend   = twrite + CHUNK_B;

    // build PWL tanh table (setup only)
    for (int k = tid; k < 1024; k += 128) {
        float x0 = -16.0f + (float)k * (1.0f / 32.0f);
        float t0 = tanhf(x0);
        float t1 = tanhf(x0 + (1.0f / 32.0f));
        float s  = (t1 - t0) * 32.0f;
        lut[k] = make_float2(s, fmaf(-s, x0, t0));
    }
    const float2* lutm512 = lut - 512;

    const float gl   = gleak[u];
    const float cmt  = cm[u] * 6.0f;
    const float glvl = gl * vleak[u];
    const float denc = cmt + gl + 1e-8f;

    // 32 per-(j,u) constants in registers
    float cs[32], cc[32], we[32];
    float Cd = 0.f, Cn = 0.f;
#pragma unroll
    for (int jj = 0; jj < 32; jj++) {
        int j   = 32 * q + jj;
        int idx = j * NU + u;
        float s = 0.5f * sigma[idx];
        cs[jj]  = s;
        cc[jj]  = -mu[idx] * s;
        float wv = 0.5f * w[idx] * erev[idx];
        we[jj]  = wv;
        Cd += fabsf(wv);
        Cn += wv;
    }

    // sensory constants: lane half q handles inputs [3q, 3q+3)
    float ss[3], sc2[3], swe[3], iw[3], ib[3];
    float sCd = 0.f, sCn = 0.f;
#pragma unroll
    for (int i = 0; i < 3; i++) {
        int ii  = 3 * q + i;
        int idx = ii * NU + u;
        float s = 0.5f * s_sigma[idx];
        ss[i]   = s;
        sc2[i]  = -s_mu[idx] * s;
        float wv = 0.5f * s_w[idx] * s_erev[idx];
        swe[i]  = wv;
        sCd += fabsf(wv);
        sCn += wv;
        iw[i] = in_w[ii];
        ib[i] = in_b[ii];
    }

    float ow = 0.f, ob = 0.f;
    if (tid < NM) { ow = out_w[tid]; ob = out_b[tid]; }

    if (q == 0) vsm[0][u + 4 * (u >> 5)] = 0.f;
    float vu = 0.f;

    const float* xb = x + (long long)b * T_LEN * NI + 3 * q;
    float* outp = out + (long long)b * T_LEN * NM;

    // sensory for the FIRST step, computed up front
    float nx0 = xb[(size_t)tstart * NI + 0];
    float nx1 = xb[(size_t)tstart * NI + 1];
    float nx2 = xb[(size_t)tstart * NI + 2];
    float den_b, num_b;
    {
        float xi0 = fmaf(nx0, iw[0], ib[0]);
        float xi1 = fmaf(nx1, iw[1], ib[1]);
        float xi2 = fmaf(nx2, iw[2], ib[2]);
        float dsa = sCd, nsa = sCn, h;
        h = fast_tanh(fmaf(xi0, ss[0], sc2[0]));
        dsa = fmaf(fabs_bits(swe[0]), h, dsa);  nsa = fmaf(swe[0], h, nsa);
        h = fast_tanh(fmaf(xi1, ss[1], sc2[1]));
        dsa = fmaf(fabs_bits(swe[1]), h, dsa);  nsa = fmaf(swe[1], h, nsa);
        h = fast_tanh(fmaf(xi2, ss[2], sc2[2]));
        dsa = fmaf(fabs_bits(swe[2]), h, dsa);  nsa = fmaf(swe[2], h, nsa);
        dsa += __shfl_xor_sync(0xffffffffu, dsa, 16);
        nsa += __shfl_xor_sync(0xffffffffu, nsa, 16);
        den_b = denc + dsa;
        num_b = glvl + nsa;
    }

    __syncthreads();

    for (int t = tstart; t < tend; t++) {
        // prefetch x(t+1); sensory(t+1) is folded into unfold k==2 below
        if (t + 1 < tend) {
            const float* xn = xb + (size_t)(t + 1) * NI;
            nx0 = xn[0]; nx1 = xn[1]; nx2 = xn[2];
        }
        float dnext = den_b, nnext = num_b;   // overwritten at k==2

        // 6 semi-implicit Euler unfolds; per float4 group: 3 MUFU + 1 LUT
#pragma unroll
        for (int k = 0; k < 6; k++) {
            const float4* vr4 =
                reinterpret_cast<const float4*>(&vsm[k & 1][rbase]);
            float an0 = Cn, an1 = 0.f, ad0 = Cd, ad1 = 0.f;
#pragma unroll
            for (int p = 0; p < 8; p++) {
                float4 v4 = vr4[p];                         // LDS.128
                float h0 = fast_tanh(fmaf(v4.x, cs[4*p],   cc[4*p]));
                float h1 = fast_tanh(fmaf(v4.y, cs[4*p+1], cc[4*p+1]));
                float h2 = fast_tanh(fmaf(v4.z, cs[4*p+2], cc[4*p+2]));
                float h3 = lut_tanh(lutm512,
                                    fmaf(v4.w, cs[4*p+3], cc[4*p+3]));
                float w0 = we[4*p],   w1 = we[4*p+1];
                float w2 = we[4*p+2], w3 = we[4*p+3];
                an0 = fmaf(w0, h0, an0);  ad0 = fmaf(fabs_bits(w0), h0, ad0);
                an1 = fmaf(w1, h1, an1);  ad1 = fmaf(fabs_bits(w1), h1, ad1);
                an0 = fmaf(w2, h2, an0);  ad0 = fmaf(fabs_bits(w2), h2, ad0);
                an1 = fmaf(w3, h3, an1);  ad1 = fmaf(fabs_bits(w3), h3, ad1);
            }

            if (k == 2) {
                // sensory for step t+1 (independent work: overlaps this
                // unfold's MUFU burst and reduce chain)
                float xi0 = fmaf(nx0, iw[0], ib[0]);
                float xi1 = fmaf(nx1, iw[1], ib[1]);
                float xi2 = fmaf(nx2, iw[2], ib[2]);
                float dsa = sCd, nsa = sCn, hs;
                hs = fast_tanh(fmaf(xi0, ss[0], sc2[0]));
                dsa = fmaf(fabs_bits(swe[0]), hs, dsa);
                nsa = fmaf(swe[0], hs, nsa);
                hs = fast_tanh(fmaf(xi1, ss[1], sc2[1]));
                dsa = fmaf(fabs_bits(swe[1]), hs, dsa);
                nsa = fmaf(swe[1], hs, nsa);
                hs = fast_tanh(fmaf(xi2, ss[2], sc2[2]));
                dsa = fmaf(fabs_bits(swe[2]), hs, dsa);
                nsa = fmaf(swe[2], hs, nsa);
                dsa += __shfl_xor_sync(0xffffffffu, dsa, 16);
                nsa += __shfl_xor_sync(0xffffffffu, nsa, 16);
                dnext = denc + dsa;
                nnext = glvl + nsa;
            }

            float an = an0 + an1, ad = ad0 + ad1;
            an += __shfl_xor_sync(0xffffffffu, an, 16);
            ad += __shfl_xor_sync(0xffffffffu, ad, 16);
            float num = fmaf(cmt, vu, num_b + an);
            vu = __fdividef(num, den_b + ad);
            if (q == 0) vsm[(k & 1) ^ 1][u + 4 * (u >> 5)] = vu;
            __syncthreads();
        }

        den_b = dnext;
        num_b = nnext;

        if (tid < NM && t >= twrite)
            outp[(size_t)t * NM + tid] = fmaf(vu, ow, ob);
    }
}

extern "C" void kernel_launch(void* const* d_in, const int* in_sizes, int n_in,
                              void* d_out, int out_size) {
    (void)in_sizes; (void)n_in; (void)out_size;
    ltc_kernel<<<256 * CHUNKS, 128>>>(
        (const float*)d_in[0],  (const float*)d_in[1],  (const float*)d_in[2],
        (const float*)d_in[3],  (const float*)d_in[4],  (const float*)d_in[5],
        (const float*)d_in[6],  (const float*)d_in[7],  (const float*)d_in[8],
        (const float*)d_in[9],  (const float*)d_in[10], (const float*)d_in[11],
        (const float*)d_in[12], (const float*)d_in[13], (const float*)d_in[14],
        (const float*)d_in[15], (float*)d_out);
}